// round 1
// baseline (speedup 1.0000x reference)
#include <cuda_runtime.h>
#include <math.h>

#define B_  4
#define S_  2048
#define D_  1024
#define H_  16
#define DH_ 64

// Scratch (allocation-free: __device__ globals). Layout [B,H,S,DH] for q,k,v; [B,S,D] for ctx.
__device__ float g_q[(size_t)B_ * H_ * S_ * DH_];
__device__ float g_k[(size_t)B_ * H_ * S_ * DH_];
__device__ float g_v[(size_t)B_ * H_ * S_ * DH_];
__device__ float g_ctx[(size_t)B_ * S_ * D_];

// ---------------------------------------------------------------------------
// 64x64x(K=1024) fp32 GEMM tile:  C[m,n] = sum_k A[m,k] * W[n,k]
// 256 threads, 4x4 microtile per thread, BK=16, transposed padded smem,
// register prefetch of next global tile.
// ---------------------------------------------------------------------------
__device__ __forceinline__ void gemm64_nt(const float* __restrict__ A,
                                          const float* __restrict__ W,
                                          float acc[4][4])
{
    __shared__ float Ast[16][68];  // [k][m], pad 68 to break store conflicts
    __shared__ float Bst[16][68];  // [k][n]

    const int tid = threadIdx.x;
    const int tx  = tid & 15;
    const int ty  = tid >> 4;
    const int lr  = tid >> 2;          // row within 64-tile this thread loads
    const int lk  = (tid & 3) << 2;    // k offset (0,4,8,12)

    const float* Ap = A + (size_t)lr * D_ + lk;
    const float* Wp = W + (size_t)lr * D_ + lk;

    float4 av = *(const float4*)Ap;
    float4 bv = *(const float4*)Wp;

#pragma unroll
    for (int i = 0; i < 4; ++i)
#pragma unroll
        for (int j = 0; j < 4; ++j) acc[i][j] = 0.0f;

#pragma unroll 1
    for (int kt = 0; kt < D_ / 16; ++kt) {
        Ast[lk + 0][lr] = av.x; Ast[lk + 1][lr] = av.y;
        Ast[lk + 2][lr] = av.z; Ast[lk + 3][lr] = av.w;
        Bst[lk + 0][lr] = bv.x; Bst[lk + 1][lr] = bv.y;
        Bst[lk + 2][lr] = bv.z; Bst[lk + 3][lr] = bv.w;
        __syncthreads();

        if (kt < D_ / 16 - 1) {
            av = *(const float4*)(Ap + (kt + 1) * 16);
            bv = *(const float4*)(Wp + (kt + 1) * 16);
        }

#pragma unroll
        for (int k = 0; k < 16; ++k) {
            float4 a4 = *(const float4*)&Ast[k][ty << 2];
            float4 b4 = *(const float4*)&Bst[k][tx << 2];
            float aa[4] = {a4.x, a4.y, a4.z, a4.w};
            float bb[4] = {b4.x, b4.y, b4.z, b4.w};
#pragma unroll
            for (int i = 0; i < 4; ++i)
#pragma unroll
                for (int j = 0; j < 4; ++j)
                    acc[i][j] = fmaf(aa[i], bb[j], acc[i][j]);
        }
        __syncthreads();
    }
}

// ---------------------------------------------------------------------------
// Fused QKV projection: q/k/v[b,h,s,dh] = sum_d x[b,s,d] * W{q,k,v}[e,d]
// grid: (N/64=16, M/64=128, 3)
// ---------------------------------------------------------------------------
__global__ void __launch_bounds__(256) qkv_gemm_kernel(const float* __restrict__ X,
                                                       const float* __restrict__ Wq,
                                                       const float* __restrict__ Wk,
                                                       const float* __restrict__ Wv)
{
    const int m0 = blockIdx.y << 6;
    const int n0 = blockIdx.x << 6;
    const float* W = (blockIdx.z == 0) ? Wq : ((blockIdx.z == 1) ? Wk : Wv);
    float* out    = (blockIdx.z == 0) ? g_q : ((blockIdx.z == 1) ? g_k : g_v);

    float acc[4][4];
    gemm64_nt(X + (size_t)m0 * D_, W + (size_t)n0 * D_, acc);

    const int tx = threadIdx.x & 15;
    const int ty = threadIdx.x >> 4;
#pragma unroll
    for (int i = 0; i < 4; ++i) {
        const int m = m0 + (ty << 2) + i;
        const int b = m >> 11;          // S_=2048
        const int s = m & (S_ - 1);
#pragma unroll
        for (int j = 0; j < 4; ++j) {
            const int n  = n0 + (tx << 2) + j;
            const int h  = n >> 6;
            const int dh = n & 63;
            out[((((size_t)b * H_ + h) * S_ + s) << 6) + dh] = acc[i][j];
        }
    }
}

// ---------------------------------------------------------------------------
// Output projection: out[b,s,e] = sum_d ctx[b,s,d] * Wo[e,d]
// grid: (16, 128)
// ---------------------------------------------------------------------------
__global__ void __launch_bounds__(256) oproj_gemm_kernel(const float* __restrict__ Wo,
                                                         float* __restrict__ Out)
{
    const int m0 = blockIdx.y << 6;
    const int n0 = blockIdx.x << 6;

    float acc[4][4];
    gemm64_nt(g_ctx + (size_t)m0 * D_, Wo + (size_t)n0 * D_, acc);

    const int tx = threadIdx.x & 15;
    const int ty = threadIdx.x >> 4;
#pragma unroll
    for (int i = 0; i < 4; ++i) {
        const int m = m0 + (ty << 2) + i;
#pragma unroll
        for (int j = 0; j < 4; ++j) {
            const int n = n0 + (tx << 2) + j;
            Out[(size_t)m * D_ + n] = acc[i][j];
        }
    }
}

// ---------------------------------------------------------------------------
// RoPE on g_q / g_k in place. One thread per (b,h,s,pair). Interleaved pairs.
// grid: (B*H*S*32/256 = 16384, 2)   blockIdx.y: 0 -> q, 1 -> k
// ---------------------------------------------------------------------------
__global__ void __launch_bounds__(256) rope_kernel(const int* __restrict__ pos)
{
    const int idx = blockIdx.x * blockDim.x + threadIdx.x;  // < B*H*S*32
    float* buf = (blockIdx.y == 0) ? g_q : g_k;

    const int p    = idx & 31;
    const int rest = idx >> 5;
    const int s    = rest & (S_ - 1);
    const int bh   = rest >> 11;
    const int b    = bh >> 4;

    float2* ptr = (float2*)(buf + (((size_t)bh * S_ + s) << 6) + (p << 1));
    float2 v = *ptr;

    const float fpos = (float)pos[b * S_ + s];
    const float inv  = powf(10000.0f, -((float)(p << 1)) / 64.0f);
    float sn, cs;
    sincosf(fpos * inv, &sn, &cs);

    float2 r;
    r.x = v.x * cs - v.y * sn;
    r.y = v.x * sn + v.y * cs;
    *ptr = r;
}

// ---------------------------------------------------------------------------
// Flash attention (causal): one CTA per (qtile of 64 rows, b*h).
// 256 threads = 8 warps. Warp w owns query rows [8w, 8w+8); lane owns output
// columns {lane, lane+32}. Scores via 16x16-thread 4x4-microtile GEMM into
// padded smem, online softmax per row, PV accumulation in registers.
// smem: Qs/Ks/Vs/Ss each [64][65] floats = 66560 B dynamic.
// ---------------------------------------------------------------------------
__global__ void __launch_bounds__(256) attn_kernel()
{
    extern __shared__ float sm[];
    float* Qs = sm;
    float* Ks = sm + 64 * 65;
    float* Vs = sm + 2 * 64 * 65;
    float* Ss = sm + 3 * 64 * 65;

    const int bh = blockIdx.y;
    const int qt = blockIdx.x;
    const int q0 = qt << 6;

    const float* Qg = g_q + ((size_t)bh * S_ << 6);
    const float* Kg = g_k + ((size_t)bh * S_ << 6);
    const float* Vg = g_v + ((size_t)bh * S_ << 6);

    const int tid  = threadIdx.x;
    const int lane = tid & 31;
    const int w    = tid >> 5;
    const int tx   = tid & 15;
    const int ty   = tid >> 4;

    // Load Q tile (scaled by 1/sqrt(DH)=0.125)
#pragma unroll
    for (int r = 0; r < 16; ++r) {
        const int e = tid + (r << 8);
        const int i = e >> 6, d = e & 63;
        Qs[i * 65 + d] = Qg[((size_t)(q0 + i) << 6) + d] * 0.125f;
    }

    float o0[8], o1[8], mrow[8], lrow[8];
#pragma unroll
    for (int ii = 0; ii < 8; ++ii) {
        o0[ii] = 0.0f; o1[ii] = 0.0f;
        mrow[ii] = -1e30f; lrow[ii] = 0.0f;
    }

#pragma unroll 1
    for (int kt = 0; kt <= qt; ++kt) {
        const int k0 = kt << 6;
        __syncthreads();  // prior PV / Q-load done before reloading tiles
#pragma unroll
        for (int r = 0; r < 16; ++r) {
            const int e = tid + (r << 8);
            const int i = e >> 6, d = e & 63;
            Ks[i * 65 + d] = Kg[((size_t)(k0 + i) << 6) + d];
            Vs[i * 65 + d] = Vg[((size_t)(k0 + i) << 6) + d];
        }
        __syncthreads();

        // Scores: S = (Q*scale) K^T over full DH=64
        float acc[4][4];
#pragma unroll
        for (int i = 0; i < 4; ++i)
#pragma unroll
            for (int j = 0; j < 4; ++j) acc[i][j] = 0.0f;

#pragma unroll
        for (int d = 0; d < 64; ++d) {
            float a[4], bb[4];
#pragma unroll
            for (int i = 0; i < 4; ++i) a[i]  = Qs[((ty << 2) + i) * 65 + d];
#pragma unroll
            for (int j = 0; j < 4; ++j) bb[j] = Ks[((tx << 2) + j) * 65 + d];
#pragma unroll
            for (int i = 0; i < 4; ++i)
#pragma unroll
                for (int j = 0; j < 4; ++j)
                    acc[i][j] = fmaf(a[i], bb[j], acc[i][j]);
        }

        // Write scores with causal mask
#pragma unroll
        for (int i = 0; i < 4; ++i) {
            const int row = (ty << 2) + i;
#pragma unroll
            for (int j = 0; j < 4; ++j) {
                const int col = (tx << 2) + j;
                float sv = acc[i][j];
                if (k0 + col > q0 + row) sv = -1e30f;
                Ss[row * 65 + col] = sv;
            }
        }
        __syncthreads();

        // Online softmax for warp-owned rows
#pragma unroll
        for (int ii = 0; ii < 8; ++ii) {
            const int row = (w << 3) + ii;
            float s0 = Ss[row * 65 + lane];
            float s1 = Ss[row * 65 + lane + 32];
            float mx = fmaxf(s0, s1);
#pragma unroll
            for (int off = 16; off > 0; off >>= 1)
                mx = fmaxf(mx, __shfl_xor_sync(0xffffffffu, mx, off));
            const float mn = fmaxf(mrow[ii], mx);
            const float sc = __expf(mrow[ii] - mn);
            const float p0 = __expf(s0 - mn);
            const float p1 = __expf(s1 - mn);
            float rs = p0 + p1;
#pragma unroll
            for (int off = 16; off > 0; off >>= 1)
                rs += __shfl_xor_sync(0xffffffffu, rs, off);
            lrow[ii] = lrow[ii] * sc + rs;
            o0[ii] *= sc;
            o1[ii] *= sc;
            mrow[ii] = mn;
            Ss[row * 65 + lane]      = p0;
            Ss[row * 65 + lane + 32] = p1;
        }
        __syncwarp();  // P written by other lanes of this warp, read below

        // PV accumulate
#pragma unroll 4
        for (int j = 0; j < 64; ++j) {
            const float v0 = Vs[j * 65 + lane];
            const float v1 = Vs[j * 65 + lane + 32];
#pragma unroll
            for (int ii = 0; ii < 8; ++ii) {
                const float p = Ss[((w << 3) + ii) * 65 + j];
                o0[ii] = fmaf(p, v0, o0[ii]);
                o1[ii] = fmaf(p, v1, o1[ii]);
            }
        }
    }

    // Epilogue -> ctx[b, s, h*64 + d]
    const int b = bh >> 4;
    const int h = bh & 15;
#pragma unroll
    for (int ii = 0; ii < 8; ++ii) {
        const int srow = q0 + (w << 3) + ii;
        const float invl = 1.0f / lrow[ii];
        const size_t base = ((size_t)(b * S_ + srow)) * D_ + (h << 6);
        g_ctx[base + lane]      = o0[ii] * invl;
        g_ctx[base + lane + 32] = o1[ii] * invl;
    }
}

// ---------------------------------------------------------------------------
// Host launcher
// ---------------------------------------------------------------------------
extern "C" void kernel_launch(void* const* d_in, const int* in_sizes, int n_in,
                              void* d_out, int out_size)
{
    const float* x   = (const float*)d_in[0];
    const int*   pos = (const int*)  d_in[1];
    const float* Wq  = (const float*)d_in[2];
    const float* Wk  = (const float*)d_in[3];
    const float* Wv  = (const float*)d_in[4];
    const float* Wo  = (const float*)d_in[5];
    float* out = (float*)d_out;

    const int ATTN_SMEM = 4 * 64 * 65 * sizeof(float);  // 66560 B
    cudaFuncSetAttribute(attn_kernel, cudaFuncAttributeMaxDynamicSharedMemorySize, ATTN_SMEM);

    // 1) QKV projections into [B,H,S,DH] scratch
    qkv_gemm_kernel<<<dim3(D_ / 64, (B_ * S_) / 64, 3), 256>>>(x, Wq, Wk, Wv);

    // 2) RoPE on q and k
    rope_kernel<<<dim3((B_ * H_ * S_ * 32) / 256, 2), 256>>>(pos);

    // 3) Causal flash attention -> ctx [B,S,D]
    attn_kernel<<<dim3(S_ / 64, B_ * H_), 256, ATTN_SMEM>>>();

    // 4) Output projection
    oproj_gemm_kernel<<<dim3(D_ / 64, (B_ * S_) / 64), 256>>>(Wo, out);
}

// round 2
// speedup vs baseline: 1.5785x; 1.5785x over previous
#include <cuda_runtime.h>
#include <math.h>
#include <stdint.h>

#define B_  4
#define S_  2048
#define D_  1024
#define H_  16
#define DH_ 64

// Scratch (allocation-free: __device__ globals). Layout [B,H,S,DH] for q,k,v; [B,S,D] for ctx.
__device__ float g_q[(size_t)B_ * H_ * S_ * DH_];
__device__ float g_k[(size_t)B_ * H_ * S_ * DH_];
__device__ float g_v[(size_t)B_ * H_ * S_ * DH_];
__device__ float g_ctx[(size_t)B_ * S_ * D_];

__device__ __forceinline__ uint32_t f2tf32(float x) {
    uint32_t u;
    asm("cvt.rna.tf32.f32 %0, %1;" : "=r"(u) : "f"(x));
    return u;
}

// ---------------------------------------------------------------------------
// TF32 tensor-core GEMM tile: C[128,128] += A[128,K] * W[128,K]^T, K=1024.
// 256 threads / 8 warps; warp tile 64x32 = 4x4 mma tiles of m16n8k8.
// Double-buffered smem stored transposed [k][m] (stride 132 -> conflict-free
// fragment loads: bank = 4*tg + g, all 32 distinct).
// ---------------------------------------------------------------------------
__device__ __forceinline__ void gemm_tf32_128(const float* __restrict__ A,
                                              const float* __restrict__ W,
                                              float acc[4][4][4])
{
    __shared__ uint32_t As[2][16][132];
    __shared__ uint32_t Bs[2][16][132];

    const int tid  = threadIdx.x;
    const int lane = tid & 31;
    const int w    = tid >> 5;
    const int wm   = (w & 1) * 64;   // warp M origin in tile
    const int wn   = (w >> 1) * 32;  // warp N origin in tile
    const int g    = lane >> 2;
    const int tg   = lane & 3;

    // Loader mapping: each thread stages 2 float4 of A and 2 of W per chunk.
    const int lr = tid >> 2;          // row 0..63 (second half = +64)
    const int lc = (tid & 3) << 2;    // col 0,4,8,12

    const float* Ap = A + (size_t)lr * D_ + lc;
    const float* Wp = W + (size_t)lr * D_ + lc;

#pragma unroll
    for (int mt = 0; mt < 4; ++mt)
#pragma unroll
        for (int nt = 0; nt < 4; ++nt)
#pragma unroll
            for (int c = 0; c < 4; ++c) acc[mt][nt][c] = 0.0f;

    float4 av0 = *(const float4*)(Ap);
    float4 av1 = *(const float4*)(Ap + (size_t)64 * D_);
    float4 bv0 = *(const float4*)(Wp);
    float4 bv1 = *(const float4*)(Wp + (size_t)64 * D_);

    int cur = 0;
#pragma unroll 1
    for (int kt = 0; kt < D_ / 16; ++kt) {
        // Store staged tile (cvt to tf32 once, here)
        const float* fa0 = (const float*)&av0;
        const float* fa1 = (const float*)&av1;
        const float* fb0 = (const float*)&bv0;
        const float* fb1 = (const float*)&bv1;
#pragma unroll
        for (int i = 0; i < 4; ++i) {
            As[cur][lc + i][lr]      = f2tf32(fa0[i]);
            As[cur][lc + i][lr + 64] = f2tf32(fa1[i]);
            Bs[cur][lc + i][lr]      = f2tf32(fb0[i]);
            Bs[cur][lc + i][lr + 64] = f2tf32(fb1[i]);
        }
        __syncthreads();

        if (kt < D_ / 16 - 1) {
            const int ko = (kt + 1) * 16;
            av0 = *(const float4*)(Ap + ko);
            av1 = *(const float4*)(Ap + ko + (size_t)64 * D_);
            bv0 = *(const float4*)(Wp + ko);
            bv1 = *(const float4*)(Wp + ko + (size_t)64 * D_);
        }

#pragma unroll
        for (int ks = 0; ks < 2; ++ks) {
            const int k0 = ks * 8;
            uint32_t af[4][4], bf[4][2];
#pragma unroll
            for (int mt = 0; mt < 4; ++mt) {
                const int m = wm + mt * 16 + g;
                af[mt][0] = As[cur][k0 + tg][m];
                af[mt][1] = As[cur][k0 + tg][m + 8];
                af[mt][2] = As[cur][k0 + tg + 4][m];
                af[mt][3] = As[cur][k0 + tg + 4][m + 8];
            }
#pragma unroll
            for (int nt = 0; nt < 4; ++nt) {
                const int n = wn + nt * 8 + g;
                bf[nt][0] = Bs[cur][k0 + tg][n];
                bf[nt][1] = Bs[cur][k0 + tg + 4][n];
            }
#pragma unroll
            for (int mt = 0; mt < 4; ++mt)
#pragma unroll
                for (int nt = 0; nt < 4; ++nt)
                    asm volatile(
                        "mma.sync.aligned.m16n8k8.row.col.f32.tf32.tf32.f32 "
                        "{%0,%1,%2,%3},{%4,%5,%6,%7},{%8,%9},{%0,%1,%2,%3};"
                        : "+f"(acc[mt][nt][0]), "+f"(acc[mt][nt][1]),
                          "+f"(acc[mt][nt][2]), "+f"(acc[mt][nt][3])
                        : "r"(af[mt][0]), "r"(af[mt][1]), "r"(af[mt][2]), "r"(af[mt][3]),
                          "r"(bf[nt][0]), "r"(bf[nt][1]));
        }
        cur ^= 1;
    }
}

// ---------------------------------------------------------------------------
// Fused QKV projection (tf32 tensor cores).
// grid: (N/128=8, M/128=64, 3)   out scatter -> [B,H,S,DH]
// ---------------------------------------------------------------------------
__global__ void __launch_bounds__(256) qkv_gemm_kernel(const float* __restrict__ X,
                                                       const float* __restrict__ Wq,
                                                       const float* __restrict__ Wk,
                                                       const float* __restrict__ Wv)
{
    const int m0 = blockIdx.y << 7;
    const int n0 = blockIdx.x << 7;
    const float* W = (blockIdx.z == 0) ? Wq : ((blockIdx.z == 1) ? Wk : Wv);
    float* out    = (blockIdx.z == 0) ? g_q : ((blockIdx.z == 1) ? g_k : g_v);

    float acc[4][4][4];
    gemm_tf32_128(X + (size_t)m0 * D_, W + (size_t)n0 * D_, acc);

    const int lane = threadIdx.x & 31;
    const int w    = threadIdx.x >> 5;
    const int wm   = (w & 1) * 64;
    const int wn   = (w >> 1) * 32;
    const int g    = lane >> 2;
    const int tg   = lane & 3;

#pragma unroll
    for (int mt = 0; mt < 4; ++mt) {
#pragma unroll
        for (int nt = 0; nt < 4; ++nt) {
            const int n  = n0 + wn + nt * 8 + tg * 2;
            const int h  = n >> 6;
            const int dh = n & 63;
#pragma unroll
            for (int half = 0; half < 2; ++half) {
                const int m = m0 + wm + mt * 16 + g + half * 8;
                const int b = m >> 11;
                const int s = m & (S_ - 1);
                float2 v;
                v.x = acc[mt][nt][half * 2 + 0];
                v.y = acc[mt][nt][half * 2 + 1];
                *(float2*)&out[((((size_t)b * H_ + h) * S_ + s) << 6) + dh] = v;
            }
        }
    }
}

// ---------------------------------------------------------------------------
// Output projection (tf32 tensor cores). grid: (8, 64)
// ---------------------------------------------------------------------------
__global__ void __launch_bounds__(256) oproj_gemm_kernel(const float* __restrict__ Wo,
                                                         float* __restrict__ Out)
{
    const int m0 = blockIdx.y << 7;
    const int n0 = blockIdx.x << 7;

    float acc[4][4][4];
    gemm_tf32_128(g_ctx + (size_t)m0 * D_, Wo + (size_t)n0 * D_, acc);

    const int lane = threadIdx.x & 31;
    const int w    = threadIdx.x >> 5;
    const int wm   = (w & 1) * 64;
    const int wn   = (w >> 1) * 32;
    const int g    = lane >> 2;
    const int tg   = lane & 3;

#pragma unroll
    for (int mt = 0; mt < 4; ++mt) {
#pragma unroll
        for (int nt = 0; nt < 4; ++nt) {
            const int n = n0 + wn + nt * 8 + tg * 2;
#pragma unroll
            for (int half = 0; half < 2; ++half) {
                const int m = m0 + wm + mt * 16 + g + half * 8;
                float2 v;
                v.x = acc[mt][nt][half * 2 + 0];
                v.y = acc[mt][nt][half * 2 + 1];
                *(float2*)&Out[(size_t)m * D_ + n] = v;
            }
        }
    }
}

// ---------------------------------------------------------------------------
// RoPE on g_q / g_k in place.
// ---------------------------------------------------------------------------
__global__ void __launch_bounds__(256) rope_kernel(const int* __restrict__ pos)
{
    const int idx = blockIdx.x * blockDim.x + threadIdx.x;
    float* buf = (blockIdx.y == 0) ? g_q : g_k;

    const int p    = idx & 31;
    const int rest = idx >> 5;
    const int s    = rest & (S_ - 1);
    const int bh   = rest >> 11;
    const int b    = bh >> 4;

    float2* ptr = (float2*)(buf + (((size_t)bh * S_ + s) << 6) + (p << 1));
    float2 v = *ptr;

    const float fpos = (float)pos[b * S_ + s];
    const float inv  = powf(10000.0f, -((float)(p << 1)) / 64.0f);
    float sn, cs;
    sincosf(fpos * inv, &sn, &cs);

    float2 r;
    r.x = v.x * cs - v.y * sn;
    r.y = v.x * sn + v.y * cs;
    *ptr = r;
}

// ---------------------------------------------------------------------------
// Flash attention (causal): one CTA per (qtile of 64 rows, b*h). fp32 math.
// ---------------------------------------------------------------------------
__global__ void __launch_bounds__(256) attn_kernel()
{
    extern __shared__ float sm[];
    float* Qs = sm;
    float* Ks = sm + 64 * 65;
    float* Vs = sm + 2 * 64 * 65;
    float* Ss = sm + 3 * 64 * 65;

    const int bh = blockIdx.y;
    const int qt = blockIdx.x;
    const int q0 = qt << 6;

    const float* Qg = g_q + ((size_t)bh * S_ << 6);
    const float* Kg = g_k + ((size_t)bh * S_ << 6);
    const float* Vg = g_v + ((size_t)bh * S_ << 6);

    const int tid  = threadIdx.x;
    const int lane = tid & 31;
    const int w    = tid >> 5;
    const int tx   = tid & 15;
    const int ty   = tid >> 4;

#pragma unroll
    for (int r = 0; r < 16; ++r) {
        const int e = tid + (r << 8);
        const int i = e >> 6, d = e & 63;
        Qs[i * 65 + d] = Qg[((size_t)(q0 + i) << 6) + d] * 0.125f;
    }

    float o0[8], o1[8], mrow[8], lrow[8];
#pragma unroll
    for (int ii = 0; ii < 8; ++ii) {
        o0[ii] = 0.0f; o1[ii] = 0.0f;
        mrow[ii] = -1e30f; lrow[ii] = 0.0f;
    }

#pragma unroll 1
    for (int kt = 0; kt <= qt; ++kt) {
        const int k0 = kt << 6;
        __syncthreads();
#pragma unroll
        for (int r = 0; r < 16; ++r) {
            const int e = tid + (r << 8);
            const int i = e >> 6, d = e & 63;
            Ks[i * 65 + d] = Kg[((size_t)(k0 + i) << 6) + d];
            Vs[i * 65 + d] = Vg[((size_t)(k0 + i) << 6) + d];
        }
        __syncthreads();

        float acc[4][4];
#pragma unroll
        for (int i = 0; i < 4; ++i)
#pragma unroll
            for (int j = 0; j < 4; ++j) acc[i][j] = 0.0f;

#pragma unroll
        for (int d = 0; d < 64; ++d) {
            float a[4], bb[4];
#pragma unroll
            for (int i = 0; i < 4; ++i) a[i]  = Qs[((ty << 2) + i) * 65 + d];
#pragma unroll
            for (int j = 0; j < 4; ++j) bb[j] = Ks[((tx << 2) + j) * 65 + d];
#pragma unroll
            for (int i = 0; i < 4; ++i)
#pragma unroll
                for (int j = 0; j < 4; ++j)
                    acc[i][j] = fmaf(a[i], bb[j], acc[i][j]);
        }

#pragma unroll
        for (int i = 0; i < 4; ++i) {
            const int row = (ty << 2) + i;
#pragma unroll
            for (int j = 0; j < 4; ++j) {
                const int col = (tx << 2) + j;
                float sv = acc[i][j];
                if (k0 + col > q0 + row) sv = -1e30f;
                Ss[row * 65 + col] = sv;
            }
        }
        __syncthreads();

#pragma unroll
        for (int ii = 0; ii < 8; ++ii) {
            const int row = (w << 3) + ii;
            float s0 = Ss[row * 65 + lane];
            float s1 = Ss[row * 65 + lane + 32];
            float mx = fmaxf(s0, s1);
#pragma unroll
            for (int off = 16; off > 0; off >>= 1)
                mx = fmaxf(mx, __shfl_xor_sync(0xffffffffu, mx, off));
            const float mn = fmaxf(mrow[ii], mx);
            const float sc = __expf(mrow[ii] - mn);
            const float p0 = __expf(s0 - mn);
            const float p1 = __expf(s1 - mn);
            float rs = p0 + p1;
#pragma unroll
            for (int off = 16; off > 0; off >>= 1)
                rs += __shfl_xor_sync(0xffffffffu, rs, off);
            lrow[ii] = lrow[ii] * sc + rs;
            o0[ii] *= sc;
            o1[ii] *= sc;
            mrow[ii] = mn;
            Ss[row * 65 + lane]      = p0;
            Ss[row * 65 + lane + 32] = p1;
        }
        __syncwarp();

#pragma unroll 4
        for (int j = 0; j < 64; ++j) {
            const float v0 = Vs[j * 65 + lane];
            const float v1 = Vs[j * 65 + lane + 32];
#pragma unroll
            for (int ii = 0; ii < 8; ++ii) {
                const float p = Ss[((w << 3) + ii) * 65 + j];
                o0[ii] = fmaf(p, v0, o0[ii]);
                o1[ii] = fmaf(p, v1, o1[ii]);
            }
        }
    }

    const int b = bh >> 4;
    const int h = bh & 15;
#pragma unroll
    for (int ii = 0; ii < 8; ++ii) {
        const int srow = q0 + (w << 3) + ii;
        const float invl = 1.0f / lrow[ii];
        const size_t base = ((size_t)(b * S_ + srow)) * D_ + (h << 6);
        g_ctx[base + lane]      = o0[ii] * invl;
        g_ctx[base + lane + 32] = o1[ii] * invl;
    }
}

// ---------------------------------------------------------------------------
// Host launcher
// ---------------------------------------------------------------------------
extern "C" void kernel_launch(void* const* d_in, const int* in_sizes, int n_in,
                              void* d_out, int out_size)
{
    const float* x   = (const float*)d_in[0];
    const int*   pos = (const int*)  d_in[1];
    const float* Wq  = (const float*)d_in[2];
    const float* Wk  = (const float*)d_in[3];
    const float* Wv  = (const float*)d_in[4];
    const float* Wo  = (const float*)d_in[5];
    float* out = (float*)d_out;

    const int ATTN_SMEM = 4 * 64 * 65 * sizeof(float);
    cudaFuncSetAttribute(attn_kernel, cudaFuncAttributeMaxDynamicSharedMemorySize, ATTN_SMEM);

    // 1) QKV projections (tf32 tensor cores) into [B,H,S,DH] scratch
    qkv_gemm_kernel<<<dim3(D_ / 128, (B_ * S_) / 128, 3), 256>>>(x, Wq, Wk, Wv);

    // 2) RoPE on q and k
    rope_kernel<<<dim3((B_ * H_ * S_ * 32) / 256, 2), 256>>>(pos);

    // 3) Causal flash attention -> ctx [B,S,D]
    attn_kernel<<<dim3(S_ / 64, B_ * H_), 256, ATTN_SMEM>>>();

    // 4) Output projection (tf32 tensor cores)
    oproj_gemm_kernel<<<dim3(D_ / 128, (B_ * S_) / 128), 256>>>(Wo, out);
}

// round 3
// speedup vs baseline: 2.1845x; 1.3839x over previous
#include <cuda_runtime.h>
#include <math.h>
#include <stdint.h>

#define B_  4
#define S_  2048
#define D_  1024
#define H_  16
#define DH_ 64

__device__ float g_q[(size_t)B_ * H_ * S_ * DH_];
__device__ float g_k[(size_t)B_ * H_ * S_ * DH_];
__device__ float g_v[(size_t)B_ * H_ * S_ * DH_];
__device__ float g_ctx[(size_t)B_ * S_ * D_];

__device__ __forceinline__ uint32_t f2tf32(float x) {
    uint32_t u;
    asm("cvt.rna.tf32.f32 %0, %1;" : "=r"(u) : "f"(x));
    return u;
}

__device__ __forceinline__ void mma_tf32(float c[4], uint32_t a0, uint32_t a1,
                                         uint32_t a2, uint32_t a3,
                                         uint32_t b0, uint32_t b1) {
    asm volatile(
        "mma.sync.aligned.m16n8k8.row.col.f32.tf32.tf32.f32 "
        "{%0,%1,%2,%3},{%4,%5,%6,%7},{%8,%9},{%0,%1,%2,%3};"
        : "+f"(c[0]), "+f"(c[1]), "+f"(c[2]), "+f"(c[3])
        : "r"(a0), "r"(a1), "r"(a2), "r"(a3), "r"(b0), "r"(b1));
}

// ---------------------------------------------------------------------------
// TF32 tensor-core GEMM tile: C[128,128] += A[128,K] * W[128,K]^T, K=1024.
// ---------------------------------------------------------------------------
__device__ __forceinline__ void gemm_tf32_128(const float* __restrict__ A,
                                              const float* __restrict__ W,
                                              float acc[4][4][4])
{
    __shared__ uint32_t As[2][16][132];
    __shared__ uint32_t Bs[2][16][132];

    const int tid  = threadIdx.x;
    const int lane = tid & 31;
    const int w    = tid >> 5;
    const int wm   = (w & 1) * 64;
    const int wn   = (w >> 1) * 32;
    const int g    = lane >> 2;
    const int tg   = lane & 3;

    const int lr = tid >> 2;
    const int lc = (tid & 3) << 2;

    const float* Ap = A + (size_t)lr * D_ + lc;
    const float* Wp = W + (size_t)lr * D_ + lc;

#pragma unroll
    for (int mt = 0; mt < 4; ++mt)
#pragma unroll
        for (int nt = 0; nt < 4; ++nt)
#pragma unroll
            for (int c = 0; c < 4; ++c) acc[mt][nt][c] = 0.0f;

    float4 av0 = *(const float4*)(Ap);
    float4 av1 = *(const float4*)(Ap + (size_t)64 * D_);
    float4 bv0 = *(const float4*)(Wp);
    float4 bv1 = *(const float4*)(Wp + (size_t)64 * D_);

    int cur = 0;
#pragma unroll 1
    for (int kt = 0; kt < D_ / 16; ++kt) {
        const float* fa0 = (const float*)&av0;
        const float* fa1 = (const float*)&av1;
        const float* fb0 = (const float*)&bv0;
        const float* fb1 = (const float*)&bv1;
#pragma unroll
        for (int i = 0; i < 4; ++i) {
            As[cur][lc + i][lr]      = f2tf32(fa0[i]);
            As[cur][lc + i][lr + 64] = f2tf32(fa1[i]);
            Bs[cur][lc + i][lr]      = f2tf32(fb0[i]);
            Bs[cur][lc + i][lr + 64] = f2tf32(fb1[i]);
        }
        __syncthreads();

        if (kt < D_ / 16 - 1) {
            const int ko = (kt + 1) * 16;
            av0 = *(const float4*)(Ap + ko);
            av1 = *(const float4*)(Ap + ko + (size_t)64 * D_);
            bv0 = *(const float4*)(Wp + ko);
            bv1 = *(const float4*)(Wp + ko + (size_t)64 * D_);
        }

#pragma unroll
        for (int ks = 0; ks < 2; ++ks) {
            const int k0 = ks * 8;
            uint32_t af[4][4], bf[4][2];
#pragma unroll
            for (int mt = 0; mt < 4; ++mt) {
                const int m = wm + mt * 16 + g;
                af[mt][0] = As[cur][k0 + tg][m];
                af[mt][1] = As[cur][k0 + tg][m + 8];
                af[mt][2] = As[cur][k0 + tg + 4][m];
                af[mt][3] = As[cur][k0 + tg + 4][m + 8];
            }
#pragma unroll
            for (int nt = 0; nt < 4; ++nt) {
                const int n = wn + nt * 8 + g;
                bf[nt][0] = Bs[cur][k0 + tg][n];
                bf[nt][1] = Bs[cur][k0 + tg + 4][n];
            }
#pragma unroll
            for (int mt = 0; mt < 4; ++mt)
#pragma unroll
                for (int nt = 0; nt < 4; ++nt)
                    mma_tf32(acc[mt][nt], af[mt][0], af[mt][1], af[mt][2], af[mt][3],
                             bf[nt][0], bf[nt][1]);
        }
        cur ^= 1;
    }
}

__global__ void __launch_bounds__(256) qkv_gemm_kernel(const float* __restrict__ X,
                                                       const float* __restrict__ Wq,
                                                       const float* __restrict__ Wk,
                                                       const float* __restrict__ Wv)
{
    const int m0 = blockIdx.y << 7;
    const int n0 = blockIdx.x << 7;
    const float* W = (blockIdx.z == 0) ? Wq : ((blockIdx.z == 1) ? Wk : Wv);
    float* out    = (blockIdx.z == 0) ? g_q : ((blockIdx.z == 1) ? g_k : g_v);

    float acc[4][4][4];
    gemm_tf32_128(X + (size_t)m0 * D_, W + (size_t)n0 * D_, acc);

    const int lane = threadIdx.x & 31;
    const int w    = threadIdx.x >> 5;
    const int wm   = (w & 1) * 64;
    const int wn   = (w >> 1) * 32;
    const int g    = lane >> 2;
    const int tg   = lane & 3;

#pragma unroll
    for (int mt = 0; mt < 4; ++mt) {
#pragma unroll
        for (int nt = 0; nt < 4; ++nt) {
            const int n  = n0 + wn + nt * 8 + tg * 2;
            const int h  = n >> 6;
            const int dh = n & 63;
#pragma unroll
            for (int half = 0; half < 2; ++half) {
                const int m = m0 + wm + mt * 16 + g + half * 8;
                const int b = m >> 11;
                const int s = m & (S_ - 1);
                float2 v;
                v.x = acc[mt][nt][half * 2 + 0];
                v.y = acc[mt][nt][half * 2 + 1];
                *(float2*)&out[((((size_t)b * H_ + h) * S_ + s) << 6) + dh] = v;
            }
        }
    }
}

__global__ void __launch_bounds__(256) oproj_gemm_kernel(const float* __restrict__ Wo,
                                                         float* __restrict__ Out)
{
    const int m0 = blockIdx.y << 7;
    const int n0 = blockIdx.x << 7;

    float acc[4][4][4];
    gemm_tf32_128(g_ctx + (size_t)m0 * D_, Wo + (size_t)n0 * D_, acc);

    const int lane = threadIdx.x & 31;
    const int w    = threadIdx.x >> 5;
    const int wm   = (w & 1) * 64;
    const int wn   = (w >> 1) * 32;
    const int g    = lane >> 2;
    const int tg   = lane & 3;

#pragma unroll
    for (int mt = 0; mt < 4; ++mt) {
#pragma unroll
        for (int nt = 0; nt < 4; ++nt) {
            const int n = n0 + wn + nt * 8 + tg * 2;
#pragma unroll
            for (int half = 0; half < 2; ++half) {
                const int m = m0 + wm + mt * 16 + g + half * 8;
                float2 v;
                v.x = acc[mt][nt][half * 2 + 0];
                v.y = acc[mt][nt][half * 2 + 1];
                *(float2*)&Out[(size_t)m * D_ + n] = v;
            }
        }
    }
}

__global__ void __launch_bounds__(256) rope_kernel(const int* __restrict__ pos)
{
    const int idx = blockIdx.x * blockDim.x + threadIdx.x;
    float* buf = (blockIdx.y == 0) ? g_q : g_k;

    const int p    = idx & 31;
    const int rest = idx >> 5;
    const int s    = rest & (S_ - 1);
    const int bh   = rest >> 11;
    const int b    = bh >> 4;

    float2* ptr = (float2*)(buf + (((size_t)bh * S_ + s) << 6) + (p << 1));
    float2 v = *ptr;

    const float fpos = (float)pos[b * S_ + s];
    const float inv  = powf(10000.0f, -((float)(p << 1)) / 64.0f);
    float sn, cs;
    sincosf(fpos * inv, &sn, &cs);

    float2 r;
    r.x = v.x * cs - v.y * sn;
    r.y = v.x * sn + v.y * cs;
    *ptr = r;
}

// ---------------------------------------------------------------------------
// Flash attention (causal) with tf32 tensor cores for QK^T and PV.
// CTA = (64 q-rows, bh). 8 warps. mma warp grid 4x2: warp owns 16 rows x 32 cols.
// smem (stride 68 words -> bank 4g+tg conflict-free fragment loads):
//   Qs[64][68] tf32, Ks[64][68] tf32, Vt[64][68] tf32 (TRANSPOSED: [d][j]),
//   Ss[64][68] scores(f32) then P(tf32), rowscale[64], rowl[64].
// ---------------------------------------------------------------------------
__global__ void __launch_bounds__(256) attn_kernel()
{
    extern __shared__ uint32_t smu[];
    uint32_t* Qs = smu;
    uint32_t* Ks = Qs + 64 * 68;
    uint32_t* Vt = Ks + 64 * 68;
    uint32_t* Ss = Vt + 64 * 68;
    float* Sf = (float*)Ss;
    float* rowscale = (float*)(Ss + 64 * 68);
    float* rowl     = rowscale + 64;

    const int bh = blockIdx.y;
    const int qt = gridDim.x - 1 - blockIdx.x;   // longest CTAs first
    const int q0 = qt << 6;

    const float* Qg = g_q + ((size_t)bh * S_ << 6);
    const float* Kg = g_k + ((size_t)bh * S_ << 6);
    const float* Vg = g_v + ((size_t)bh * S_ << 6);

    const int tid  = threadIdx.x;
    const int lane = tid & 31;
    const int w    = tid >> 5;
    const int g    = lane >> 2;
    const int tg   = lane & 3;
    const int m0w  = (w & 3) * 16;   // mma warp row origin
    const int n0w  = (w >> 2) * 32;  // mma warp col origin (scores) / d origin (PV)

    // Q tile -> smem tf32, pre-scaled
#pragma unroll
    for (int r = 0; r < 16; ++r) {
        const int e = tid + (r << 8);
        const int i = e >> 6, d = e & 63;
        Qs[i * 68 + d] = f2tf32(Qg[((size_t)(q0 + i) << 6) + d] * 0.125f);
    }

    float o[4][4];     // O accumulator: [ntile(d/8)][c]
    float mrow[8], lrow[8];
#pragma unroll
    for (int nt = 0; nt < 4; ++nt)
#pragma unroll
        for (int c = 0; c < 4; ++c) o[nt][c] = 0.0f;
#pragma unroll
    for (int ii = 0; ii < 8; ++ii) { mrow[ii] = -1e30f; lrow[ii] = 0.0f; }

#pragma unroll 1
    for (int kt = 0; kt <= qt; ++kt) {
        const int k0 = kt << 6;
        __syncthreads();
        // K tile [n][d], V tile TRANSPOSED [d][j]
#pragma unroll
        for (int r = 0; r < 16; ++r) {
            const int e = tid + (r << 8);
            const int i = e >> 6, d = e & 63;
            Ks[i * 68 + d] = f2tf32(Kg[((size_t)(k0 + i) << 6) + d]);
            Vt[d * 68 + i] = f2tf32(Vg[((size_t)(k0 + i) << 6) + d]);
        }
        __syncthreads();

        // Scores: S[m][n] = Q . K^T  (4 n-tiles per warp)
        float acc[4][4];
#pragma unroll
        for (int nt = 0; nt < 4; ++nt)
#pragma unroll
            for (int c = 0; c < 4; ++c) acc[nt][c] = 0.0f;

#pragma unroll
        for (int ks = 0; ks < 8; ++ks) {
            const int d0 = ks * 8;
            const uint32_t a0 = Qs[(m0w + g) * 68 + d0 + tg];
            const uint32_t a1 = Qs[(m0w + g + 8) * 68 + d0 + tg];
            const uint32_t a2 = Qs[(m0w + g) * 68 + d0 + tg + 4];
            const uint32_t a3 = Qs[(m0w + g + 8) * 68 + d0 + tg + 4];
#pragma unroll
            for (int nt = 0; nt < 4; ++nt) {
                const uint32_t b0 = Ks[(n0w + nt * 8 + g) * 68 + d0 + tg];
                const uint32_t b1 = Ks[(n0w + nt * 8 + g) * 68 + d0 + tg + 4];
                mma_tf32(acc[nt], a0, a1, a2, a3, b0, b1);
            }
        }

        // Write scores to smem with causal mask
#pragma unroll
        for (int nt = 0; nt < 4; ++nt) {
            const int col = n0w + nt * 8 + tg * 2;
            const int ct0 = k0 + col;
#pragma unroll
            for (int half = 0; half < 2; ++half) {
                const int row = m0w + g + half * 8;
                const int rt  = q0 + row;
                Sf[row * 68 + col]     = (ct0     <= rt) ? acc[nt][half * 2]     : -1e30f;
                Sf[row * 68 + col + 1] = (ct0 + 1 <= rt) ? acc[nt][half * 2 + 1] : -1e30f;
            }
        }
        __syncthreads();

        // Online softmax: warp w owns rows [8w, 8w+8)
#pragma unroll
        for (int ii = 0; ii < 8; ++ii) {
            const int row = (w << 3) + ii;
            float s0 = Sf[row * 68 + lane];
            float s1 = Sf[row * 68 + lane + 32];
            float mx = fmaxf(s0, s1);
#pragma unroll
            for (int off = 16; off > 0; off >>= 1)
                mx = fmaxf(mx, __shfl_xor_sync(0xffffffffu, mx, off));
            const float mn = fmaxf(mrow[ii], mx);
            const float sc = __expf(mrow[ii] - mn);
            const float p0 = __expf(s0 - mn);
            const float p1 = __expf(s1 - mn);
            float rs = p0 + p1;
#pragma unroll
            for (int off = 16; off > 0; off >>= 1)
                rs += __shfl_xor_sync(0xffffffffu, rs, off);
            lrow[ii] = lrow[ii] * sc + rs;
            mrow[ii] = mn;
            Ss[row * 68 + lane]      = f2tf32(p0);
            Ss[row * 68 + lane + 32] = f2tf32(p1);
            if (lane == 0) rowscale[row] = sc;
        }
        __syncthreads();

        // Rescale O accumulators by this tile's row scale
        const float sc0 = rowscale[m0w + g];
        const float sc1 = rowscale[m0w + g + 8];
#pragma unroll
        for (int nt = 0; nt < 4; ++nt) {
            o[nt][0] *= sc0; o[nt][1] *= sc0;
            o[nt][2] *= sc1; o[nt][3] *= sc1;
        }

        // PV: O[m][d] += P[m][j] * V[j][d]   (B frags from transposed Vt)
#pragma unroll
        for (int ks = 0; ks < 8; ++ks) {
            const int j0 = ks * 8;
            const uint32_t a0 = Ss[(m0w + g) * 68 + j0 + tg];
            const uint32_t a1 = Ss[(m0w + g + 8) * 68 + j0 + tg];
            const uint32_t a2 = Ss[(m0w + g) * 68 + j0 + tg + 4];
            const uint32_t a3 = Ss[(m0w + g + 8) * 68 + j0 + tg + 4];
#pragma unroll
            for (int nt = 0; nt < 4; ++nt) {
                const uint32_t b0 = Vt[(n0w + nt * 8 + g) * 68 + j0 + tg];
                const uint32_t b1 = Vt[(n0w + nt * 8 + g) * 68 + j0 + tg + 4];
                mma_tf32(o[nt], a0, a1, a2, a3, b0, b1);
            }
        }
    }

    // Publish row sums, then epilogue
#pragma unroll
    for (int ii = 0; ii < 8; ++ii)
        if (lane == 0) rowl[(w << 3) + ii] = lrow[ii];
    __syncthreads();

    const int b = bh >> 4;
    const int h = bh & 15;
    const float invl0 = 1.0f / rowl[m0w + g];
    const float invl1 = 1.0f / rowl[m0w + g + 8];
#pragma unroll
    for (int nt = 0; nt < 4; ++nt) {
        const int col = (h << 6) + n0w + nt * 8 + tg * 2;
#pragma unroll
        for (int half = 0; half < 2; ++half) {
            const int srow = q0 + m0w + g + half * 8;
            const float iv = half ? invl1 : invl0;
            float2 v;
            v.x = o[nt][half * 2]     * iv;
            v.y = o[nt][half * 2 + 1] * iv;
            *(float2*)&g_ctx[((size_t)(b * S_ + srow)) * D_ + col] = v;
        }
    }
}

extern "C" void kernel_launch(void* const* d_in, const int* in_sizes, int n_in,
                              void* d_out, int out_size)
{
    const float* x   = (const float*)d_in[0];
    const int*   pos = (const int*)  d_in[1];
    const float* Wq  = (const float*)d_in[2];
    const float* Wk  = (const float*)d_in[3];
    const float* Wv  = (const float*)d_in[4];
    const float* Wo  = (const float*)d_in[5];
    float* out = (float*)d_out;

    const int ATTN_SMEM = (4 * 64 * 68 + 128) * sizeof(uint32_t);  // 70144 B
    cudaFuncSetAttribute(attn_kernel, cudaFuncAttributeMaxDynamicSharedMemorySize, ATTN_SMEM);

    qkv_gemm_kernel<<<dim3(D_ / 128, (B_ * S_) / 128, 3), 256>>>(x, Wq, Wk, Wv);
    rope_kernel<<<dim3((B_ * H_ * S_ * 32) / 256, 2), 256>>>(pos);
    attn_kernel<<<dim3(S_ / 64, B_ * H_), 256, ATTN_SMEM>>>();
    oproj_gemm_kernel<<<dim3(D_ / 128, (B_ * S_) / 128), 256>>>(Wo, out);
}

// round 5
// speedup vs baseline: 2.7210x; 1.2456x over previous
#include <cuda_runtime.h>
#include <math.h>
#include <stdint.h>

#define B_  4
#define S_  2048
#define D_  1024
#define H_  16
#define DH_ 64

__device__ float g_q[(size_t)B_ * H_ * S_ * DH_];
__device__ float g_k[(size_t)B_ * H_ * S_ * DH_];
__device__ float g_v[(size_t)B_ * H_ * S_ * DH_];
__device__ float g_ctx[(size_t)B_ * S_ * D_];

__device__ __forceinline__ uint32_t f2tf32(float x) {
    uint32_t u;
    asm("cvt.rna.tf32.f32 %0, %1;" : "=r"(u) : "f"(x));
    return u;
}

__device__ __forceinline__ void mma_tf32(float c[4], uint32_t a0, uint32_t a1,
                                         uint32_t a2, uint32_t a3,
                                         uint32_t b0, uint32_t b1) {
    asm volatile(
        "mma.sync.aligned.m16n8k8.row.col.f32.tf32.tf32.f32 "
        "{%0,%1,%2,%3},{%4,%5,%6,%7},{%8,%9},{%0,%1,%2,%3};"
        : "+f"(c[0]), "+f"(c[1]), "+f"(c[2]), "+f"(c[3])
        : "r"(a0), "r"(a1), "r"(a2), "r"(a3), "r"(b0), "r"(b1));
}

// ---------------------------------------------------------------------------
// TF32 tensor-core GEMM tile: C[128,128] += A[128,K] * W[128,K]^T, K=1024.
// 256 threads / 8 warps; warp tile 64x32. Double-buffered smem [k][m] stride 132.
// ---------------------------------------------------------------------------
__device__ __forceinline__ void gemm_tf32_128(const float* __restrict__ A,
                                              const float* __restrict__ W,
                                              float acc[4][4][4])
{
    __shared__ uint32_t As[2][16][132];
    __shared__ uint32_t Bs[2][16][132];

    const int tid  = threadIdx.x;
    const int lane = tid & 31;
    const int w    = tid >> 5;
    const int wm   = (w & 1) * 64;
    const int wn   = (w >> 1) * 32;
    const int g    = lane >> 2;
    const int tg   = lane & 3;

    const int lr = tid >> 2;
    const int lc = (tid & 3) << 2;

    const float* Ap = A + (size_t)lr * D_ + lc;
    const float* Wp = W + (size_t)lr * D_ + lc;

#pragma unroll
    for (int mt = 0; mt < 4; ++mt)
#pragma unroll
        for (int nt = 0; nt < 4; ++nt)
#pragma unroll
            for (int c = 0; c < 4; ++c) acc[mt][nt][c] = 0.0f;

    float4 av0 = *(const float4*)(Ap);
    float4 av1 = *(const float4*)(Ap + (size_t)64 * D_);
    float4 bv0 = *(const float4*)(Wp);
    float4 bv1 = *(const float4*)(Wp + (size_t)64 * D_);

    int cur = 0;
#pragma unroll 1
    for (int kt = 0; kt < D_ / 16; ++kt) {
        const float* fa0 = (const float*)&av0;
        const float* fa1 = (const float*)&av1;
        const float* fb0 = (const float*)&bv0;
        const float* fb1 = (const float*)&bv1;
#pragma unroll
        for (int i = 0; i < 4; ++i) {
            As[cur][lc + i][lr]      = f2tf32(fa0[i]);
            As[cur][lc + i][lr + 64] = f2tf32(fa1[i]);
            Bs[cur][lc + i][lr]      = f2tf32(fb0[i]);
            Bs[cur][lc + i][lr + 64] = f2tf32(fb1[i]);
        }
        __syncthreads();

        if (kt < D_ / 16 - 1) {
            const int ko = (kt + 1) * 16;
            av0 = *(const float4*)(Ap + ko);
            av1 = *(const float4*)(Ap + ko + (size_t)64 * D_);
            bv0 = *(const float4*)(Wp + ko);
            bv1 = *(const float4*)(Wp + ko + (size_t)64 * D_);
        }

#pragma unroll
        for (int ks = 0; ks < 2; ++ks) {
            const int k0 = ks * 8;
            uint32_t af[4][4], bf[4][2];
#pragma unroll
            for (int mt = 0; mt < 4; ++mt) {
                const int m = wm + mt * 16 + g;
                af[mt][0] = As[cur][k0 + tg][m];
                af[mt][1] = As[cur][k0 + tg][m + 8];
                af[mt][2] = As[cur][k0 + tg + 4][m];
                af[mt][3] = As[cur][k0 + tg + 4][m + 8];
            }
#pragma unroll
            for (int nt = 0; nt < 4; ++nt) {
                const int n = wn + nt * 8 + g;
                bf[nt][0] = Bs[cur][k0 + tg][n];
                bf[nt][1] = Bs[cur][k0 + tg + 4][n];
            }
#pragma unroll
            for (int mt = 0; mt < 4; ++mt)
#pragma unroll
                for (int nt = 0; nt < 4; ++nt)
                    mma_tf32(acc[mt][nt], af[mt][0], af[mt][1], af[mt][2], af[mt][3],
                             bf[nt][0], bf[nt][1]);
        }
        cur ^= 1;
    }
}

// ---------------------------------------------------------------------------
// Fused QKV projection + RoPE epilogue (q,k rotated in-register before store).
// grid: (8, 64, 3)
// ---------------------------------------------------------------------------
__global__ void __launch_bounds__(256) qkv_gemm_kernel(const float* __restrict__ X,
                                                       const float* __restrict__ Wq,
                                                       const float* __restrict__ Wk,
                                                       const float* __restrict__ Wv,
                                                       const int* __restrict__ pos)
{
    __shared__ float s_inv[32];
    if (threadIdx.x < 32)
        s_inv[threadIdx.x] = powf(10000.0f, -((float)(threadIdx.x * 2)) / 64.0f);

    const int m0 = blockIdx.y << 7;
    const int n0 = blockIdx.x << 7;
    const float* W = (blockIdx.z == 0) ? Wq : ((blockIdx.z == 1) ? Wk : Wv);
    float* out    = (blockIdx.z == 0) ? g_q : ((blockIdx.z == 1) ? g_k : g_v);
    const bool doRope = (blockIdx.z < 2);

    float acc[4][4][4];
    gemm_tf32_128(X + (size_t)m0 * D_, W + (size_t)n0 * D_, acc);

    const int lane = threadIdx.x & 31;
    const int w    = threadIdx.x >> 5;
    const int wm   = (w & 1) * 64;
    const int wn   = (w >> 1) * 32;
    const int g    = lane >> 2;
    const int tg   = lane & 3;

#pragma unroll
    for (int mt = 0; mt < 4; ++mt) {
#pragma unroll
        for (int half = 0; half < 2; ++half) {
            const int m = m0 + wm + mt * 16 + g + half * 8;
            const int b = m >> 11;
            const int s = m & (S_ - 1);
            const float fpos = doRope ? (float)pos[b * S_ + s] : 0.0f;
#pragma unroll
            for (int nt = 0; nt < 4; ++nt) {
                const int n  = n0 + wn + nt * 8 + tg * 2;
                const int h  = n >> 6;
                const int dh = n & 63;
                float2 v;
                v.x = acc[mt][nt][half * 2 + 0];
                v.y = acc[mt][nt][half * 2 + 1];
                if (doRope) {
                    const float ang = fpos * s_inv[dh >> 1];
                    float sn, cs;
                    sincosf(ang, &sn, &cs);
                    const float rx = v.x * cs - v.y * sn;
                    const float ry = v.x * sn + v.y * cs;
                    v.x = rx; v.y = ry;
                }
                *(float2*)&out[((((size_t)b * H_ + h) * S_ + s) << 6) + dh] = v;
            }
        }
    }
}

// ---------------------------------------------------------------------------
// Output projection. grid: (8, 64)
// ---------------------------------------------------------------------------
__global__ void __launch_bounds__(256) oproj_gemm_kernel(const float* __restrict__ Wo,
                                                         float* __restrict__ Out)
{
    const int m0 = blockIdx.y << 7;
    const int n0 = blockIdx.x << 7;

    float acc[4][4][4];
    gemm_tf32_128(g_ctx + (size_t)m0 * D_, Wo + (size_t)n0 * D_, acc);

    const int lane = threadIdx.x & 31;
    const int w    = threadIdx.x >> 5;
    const int wm   = (w & 1) * 64;
    const int wn   = (w >> 1) * 32;
    const int g    = lane >> 2;
    const int tg   = lane & 3;

#pragma unroll
    for (int mt = 0; mt < 4; ++mt) {
#pragma unroll
        for (int nt = 0; nt < 4; ++nt) {
            const int n = n0 + wn + nt * 8 + tg * 2;
#pragma unroll
            for (int half = 0; half < 2; ++half) {
                const int m = m0 + wm + mt * 16 + g + half * 8;
                float2 v;
                v.x = acc[mt][nt][half * 2 + 0];
                v.y = acc[mt][nt][half * 2 + 1];
                *(float2*)&Out[(size_t)m * D_ + n] = v;
            }
        }
    }
}

// ---------------------------------------------------------------------------
// Flash attention v2 (causal, tf32 mma):
//  - CTA = 128 q-rows x (b*h); 8 warps; warp w owns rows [16w, 16w+16) x all 64 cols.
//  - K-tiles of 64. Register-resident online softmax (quad shfl over tg lanes).
//  - Single P smem write per tile, consumed intra-warp (no extra block sync).
// smem: Qs[128][68] + Ks[64][68] + Vt[64][68] + Ps[128][68] = 104448 B.
// ---------------------------------------------------------------------------
__global__ void __launch_bounds__(256) attn_kernel()
{
    extern __shared__ uint32_t smu[];
    uint32_t* Qs = smu;               // [128][68] tf32
    uint32_t* Ks = Qs + 128 * 68;     // [64][68]  tf32  (K[n][d])
    uint32_t* Vt = Ks + 64 * 68;      // [64][68]  tf32  (V transposed: [d][j])
    uint32_t* Ps = Vt + 64 * 68;      // [128][68] tf32  (P[m][j])

    const int bh = blockIdx.y;
    const int qt = gridDim.x - 1 - blockIdx.x;   // heavy tiles first
    const int q0 = qt << 7;

    const float* Qg = g_q + ((size_t)bh * S_ << 6);
    const float* Kg = g_k + ((size_t)bh * S_ << 6);
    const float* Vg = g_v + ((size_t)bh * S_ << 6);

    const int tid  = threadIdx.x;
    const int lane = tid & 31;
    const int w    = tid >> 5;
    const int g    = lane >> 2;
    const int tg   = lane & 3;
    const int rw   = w << 4;           // warp row origin
    const int r0   = rw + g;           // this thread's row A
    const int r1   = rw + g + 8;       // this thread's row B

    // Load Q tile (scaled), tf32
#pragma unroll
    for (int r = 0; r < 32; ++r) {
        const int e = tid + (r << 8);
        const int i = e >> 6, d = e & 63;
        Qs[i * 68 + d] = f2tf32(Qg[((size_t)(q0 + i) << 6) + d] * 0.125f);
    }

    float o[8][4];
#pragma unroll
    for (int nt = 0; nt < 8; ++nt)
#pragma unroll
        for (int c = 0; c < 4; ++c) o[nt][c] = 0.0f;
    float m0r = -1e30f, m1r = -1e30f, l0r = 0.0f, l1r = 0.0f;

    const int nkt = 2 * qt + 2;
#pragma unroll 1
    for (int kt = 0; kt < nkt; ++kt) {
        const int k0 = kt << 6;

        __syncthreads();   // previous iteration done reading Ks/Vt
#pragma unroll
        for (int r = 0; r < 16; ++r) {
            const int e = tid + (r << 8);
            const int i = e >> 6, d = e & 63;
            Ks[i * 68 + d] = f2tf32(Kg[((size_t)(k0 + i) << 6) + d]);
            Vt[d * 68 + i] = f2tf32(Vg[((size_t)(k0 + i) << 6) + d]);
        }
        __syncthreads();

        // Scores: acc[nt] covers cols [nt*8, nt*8+8) for rows r0/r1
        float acc[8][4];
#pragma unroll
        for (int nt = 0; nt < 8; ++nt)
#pragma unroll
            for (int c = 0; c < 4; ++c) acc[nt][c] = 0.0f;

#pragma unroll
        for (int ks = 0; ks < 8; ++ks) {
            const int d0 = ks * 8;
            const uint32_t a0 = Qs[r0 * 68 + d0 + tg];
            const uint32_t a1 = Qs[r1 * 68 + d0 + tg];
            const uint32_t a2 = Qs[r0 * 68 + d0 + tg + 4];
            const uint32_t a3 = Qs[r1 * 68 + d0 + tg + 4];
#pragma unroll
            for (int nt = 0; nt < 8; ++nt) {
                const uint32_t b0 = Ks[(nt * 8 + g) * 68 + d0 + tg];
                const uint32_t b1 = Ks[(nt * 8 + g) * 68 + d0 + tg + 4];
                mma_tf32(acc[nt], a0, a1, a2, a3, b0, b1);
            }
        }

        // Causal mask (only the last two k-tiles can clip)
        if (kt >= 2 * qt) {
            const int row0 = q0 + r0;
            const int row1 = q0 + r1;
#pragma unroll
            for (int nt = 0; nt < 8; ++nt) {
#pragma unroll
                for (int cc = 0; cc < 2; ++cc) {
                    const int col = k0 + nt * 8 + tg * 2 + cc;
                    if (col > row0) acc[nt][cc]     = -1e30f;
                    if (col > row1) acc[nt][cc + 2] = -1e30f;
                }
            }
        }

        // Register online softmax (row r0 spread over 4 tg-lanes; quad shfl)
        float mx0 = -1e30f, mx1 = -1e30f;
#pragma unroll
        for (int nt = 0; nt < 8; ++nt) {
            mx0 = fmaxf(mx0, fmaxf(acc[nt][0], acc[nt][1]));
            mx1 = fmaxf(mx1, fmaxf(acc[nt][2], acc[nt][3]));
        }
        mx0 = fmaxf(mx0, __shfl_xor_sync(0xffffffffu, mx0, 1));
        mx0 = fmaxf(mx0, __shfl_xor_sync(0xffffffffu, mx0, 2));
        mx1 = fmaxf(mx1, __shfl_xor_sync(0xffffffffu, mx1, 1));
        mx1 = fmaxf(mx1, __shfl_xor_sync(0xffffffffu, mx1, 2));

        const float mn0 = fmaxf(m0r, mx0);
        const float mn1 = fmaxf(m1r, mx1);
        const float sc0 = __expf(m0r - mn0);
        const float sc1 = __expf(m1r - mn1);

        float rs0 = 0.0f, rs1 = 0.0f;
#pragma unroll
        for (int nt = 0; nt < 8; ++nt) {
            const float p00 = __expf(acc[nt][0] - mn0);
            const float p01 = __expf(acc[nt][1] - mn0);
            const float p10 = __expf(acc[nt][2] - mn1);
            const float p11 = __expf(acc[nt][3] - mn1);
            rs0 += p00 + p01;
            rs1 += p10 + p11;
            const int cb = nt * 8 + tg * 2;
            Ps[r0 * 68 + cb]     = f2tf32(p00);
            Ps[r0 * 68 + cb + 1] = f2tf32(p01);
            Ps[r1 * 68 + cb]     = f2tf32(p10);
            Ps[r1 * 68 + cb + 1] = f2tf32(p11);
        }
        rs0 += __shfl_xor_sync(0xffffffffu, rs0, 1);
        rs0 += __shfl_xor_sync(0xffffffffu, rs0, 2);
        rs1 += __shfl_xor_sync(0xffffffffu, rs1, 1);
        rs1 += __shfl_xor_sync(0xffffffffu, rs1, 2);

        l0r = l0r * sc0 + rs0;
        l1r = l1r * sc1 + rs1;
        m0r = mn0;
        m1r = mn1;

#pragma unroll
        for (int nt = 0; nt < 8; ++nt) {
            o[nt][0] *= sc0; o[nt][1] *= sc0;
            o[nt][2] *= sc1; o[nt][3] *= sc1;
        }

        __syncwarp();   // P rows of this warp written by its own lanes

        // PV: O[r][dh] += P[r][j] * V[j][dh]
#pragma unroll
        for (int js = 0; js < 8; ++js) {
            const int j0 = js * 8;
            const uint32_t a0 = Ps[r0 * 68 + j0 + tg];
            const uint32_t a1 = Ps[r1 * 68 + j0 + tg];
            const uint32_t a2 = Ps[r0 * 68 + j0 + tg + 4];
            const uint32_t a3 = Ps[r1 * 68 + j0 + tg + 4];
#pragma unroll
            for (int nt = 0; nt < 8; ++nt) {
                const uint32_t b0 = Vt[(nt * 8 + g) * 68 + j0 + tg];
                const uint32_t b1 = Vt[(nt * 8 + g) * 68 + j0 + tg + 4];
                mma_tf32(o[nt], a0, a1, a2, a3, b0, b1);
            }
        }
    }

    // Epilogue -> ctx[b, s, h*64 + dh]
    const int b = bh >> 4;
    const int h = bh & 15;
    const float invl0 = 1.0f / l0r;
    const float invl1 = 1.0f / l1r;
#pragma unroll
    for (int nt = 0; nt < 8; ++nt) {
        const int col = (h << 6) + nt * 8 + tg * 2;
        float2 v0, v1;
        v0.x = o[nt][0] * invl0; v0.y = o[nt][1] * invl0;
        v1.x = o[nt][2] * invl1; v1.y = o[nt][3] * invl1;
        *(float2*)&g_ctx[((size_t)(b * S_ + q0 + r0)) * D_ + col] = v0;
        *(float2*)&g_ctx[((size_t)(b * S_ + q0 + r1)) * D_ + col] = v1;
    }
}

// ---------------------------------------------------------------------------
// Host launcher
// ---------------------------------------------------------------------------
extern "C" void kernel_launch(void* const* d_in, const int* in_sizes, int n_in,
                              void* d_out, int out_size)
{
    const float* x   = (const float*)d_in[0];
    const int*   pos = (const int*)  d_in[1];
    const float* Wq  = (const float*)d_in[2];
    const float* Wk  = (const float*)d_in[3];
    const float* Wv  = (const float*)d_in[4];
    const float* Wo  = (const float*)d_in[5];
    float* out = (float*)d_out;

    const int ATTN_SMEM = (128 + 64 + 64 + 128) * 68 * sizeof(uint32_t);  // 104448 B
    cudaFuncSetAttribute(attn_kernel, cudaFuncAttributeMaxDynamicSharedMemorySize, ATTN_SMEM);

    qkv_gemm_kernel<<<dim3(D_ / 128, (B_ * S_) / 128, 3), 256>>>(x, Wq, Wk, Wv, pos);
    attn_kernel<<<dim3(S_ / 128, B_ * H_), 256, ATTN_SMEM>>>();
    oproj_gemm_kernel<<<dim3(D_ / 128, (B_ * S_) / 128), 256>>>(Wo, out);
}